// round 14
// baseline (speedup 1.0000x reference)
#include <cuda_runtime.h>
#include <math.h>
#include <cstdint>

// Problem constants
#define NBLK 512
#define BQ   32
#define HH   16
#define DD   576
#define DD4  144
#define DVV  512
#define BSS  128
#define QSCALE 0.07216878364870322f  // 192^-0.5

typedef unsigned long long ull;

// Scratch (device globals — no allocation allowed)
__device__ float g_oacc[NBLK * HH * DVV];
__device__ float g_bm[NBLK * HH];
__device__ float g_bs[NBLK * HH];

// ---------------- helpers ----------------
__device__ __forceinline__ uint32_t smem_u32(const void* p) {
    uint32_t a;
    asm("{ .reg .u64 t; cvta.to.shared.u64 t, %1; cvt.u32.u64 %0, t; }" : "=r"(a) : "l"(p));
    return a;
}
__device__ __forceinline__ void cp16(uint32_t dst, const void* src) {
    asm volatile("cp.async.cg.shared.global [%0], [%1], 16;" :: "r"(dst), "l"(src));
}
#define CP_COMMIT() asm volatile("cp.async.commit_group;" ::: "memory")
#define CP_WAIT(n)  asm volatile("cp.async.wait_group %0;" :: "n"(n) : "memory")

__device__ __forceinline__ void fma2(ull& d, ull a, ull b) {
    asm("fma.rn.f32x2 %0, %1, %2, %0;" : "+l"(d) : "l"(a), "l"(b));
}
__device__ __forceinline__ float lo_f(ull v) { return __uint_as_float((unsigned)v); }
__device__ __forceinline__ float hi_f(ull v) { return __uint_as_float((unsigned)(v >> 32)); }
__device__ __forceinline__ ull dup2(float v) {
    unsigned u = __float_as_uint(v);
    return ((ull)u << 32) | u;
}

// ---------------- SMEM layout (bytes) ----------------
// tile double buffer : 2 x (16 rows x 145 f4) = 74240      [0, 74240)
// parts              : 256 cells x 9 f = 9216               [74240, 83456)
// pp                 : 16 x 17 f = 1088                     [83456, 84544)
// Mx/Lx/rr           : 3 x 16 f                             [84544, 84736)
#define TSTR  145
#define TILEB 37120
#define PARTOFF 74240
#define PPOFF 83456
#define MOFF  84544
#define LOFF  84608
#define RROFF 84672
#define SMEM_BYTES 84736

__global__ __launch_bounds__(256, 2) void mla_fused_kernel(
    const float* __restrict__ query,
    const float* __restrict__ key_cache,
    const float* __restrict__ block_bias,
    const int* __restrict__ block_list,
    const int* __restrict__ block_groups)
{
    extern __shared__ char smem[];
    const uint32_t sbase = smem_u32(smem);
    const int t = threadIdx.x;
    const int n0 = 2 * blockIdx.x;
    const int n1 = n0 + 1;
    const int b = block_groups[n0];   // n0,n1 in the same group of 16

    const float4* kv0 = (const float4*)(key_cache + (long)block_list[n0] * (BSS * DD));
    const float4* kv1 = (const float4*)(key_cache + (long)block_list[n1] * (BSS * DD));
    const float4* qg  = (const float4*)query + (long)(b * HH) * DD4;

    float* parts = (float*)(smem + PARTOFF);
    float* pp    = (float*)(smem + PPOFF);
    float* Mx    = (float*)(smem + MOFF);
    float* Lx    = (float*)(smem + LOFF);
    float* rr    = (float*)(smem + RROFF);

    if (t < 16) { Mx[t] = -3e38f; Lx[t] = 0.f; }

    // ---- tile loader: 16 rows x 144 f4 into buffer tl&1 (tl 0..15)
    auto issueT = [&](int tl) {
        const float4* src = (tl < 8) ? kv0 : kv1;
        uint32_t tb = sbase + (unsigned)(tl & 1) * TILEB;
        int rbase = (tl & 7) * 16;
        #pragma unroll
        for (int j = 0; j < 9; j++) {
            int idx = t + j * 256;
            int row = idx / 144, col = idx - row * 144;
            cp16(tb + (unsigned)(row * TSTR + col) * 16,
                 src + (long)(rbase + row) * DD4 + col);
        }
        CP_COMMIT();
    };
    issueT(0);
    issueT(1);

    // QK maps: warp owns d-group g (18 f4 = 72 d); cells 4h x 2s per thread
    const int g  = t >> 5;       // 0..7
    const int u  = t & 31;
    const int hq = u & 3;        // h = hq + 4i
    const int sq = u >> 2;       // s = sq + 8j

    // softmax map: thread t owns cell (h = t>>4, s = t&15)
    const int sh = t >> 4, ss = t & 15;

    // PV map: h = hb + 4i; v f4 cols {vb, vb+64}
    const int hb = t & 3;
    const int vb = t >> 2;       // 0..63

    ull o2[4][4];
    #pragma unroll
    for (int i = 0; i < 4; i++)
        #pragma unroll
        for (int k = 0; k < 4; k++) o2[i][k] = 0ull;

    for (int tl = 0; tl < 16; tl++) {
        if (tl < 15) { CP_WAIT(1); } else { CP_WAIT(0); }
        __syncthreads();
        const float4* kt = (const float4*)(smem + (tl & 1) * TILEB);

        // ---- QK partials: acc[4h][2s] over d-window [g*72, g*72+72)
        {
            ull acc[4][2];
            #pragma unroll
            for (int i = 0; i < 4; i++) { acc[i][0] = 0ull; acc[i][1] = 0ull; }

            #pragma unroll
            for (int k4 = 0; k4 < 18; k4++) {
                int col = g * 18 + k4;
                ull qp[4][2], kp[2][2];
                #pragma unroll
                for (int i = 0; i < 4; i++) {
                    ulonglong2 qq = *(const ulonglong2*)&qg[(hq + 4 * i) * DD4 + col];
                    qp[i][0] = qq.x; qp[i][1] = qq.y;
                }
                #pragma unroll
                for (int j = 0; j < 2; j++) {
                    ulonglong2 kk = *(const ulonglong2*)&kt[(sq + 8 * j) * TSTR + col];
                    kp[j][0] = kk.x; kp[j][1] = kk.y;
                }
                #pragma unroll
                for (int i = 0; i < 4; i++)
                    #pragma unroll
                    for (int j = 0; j < 2; j++) {
                        fma2(acc[i][j], qp[i][0], kp[j][0]);
                        fma2(acc[i][j], qp[i][1], kp[j][1]);
                    }
            }
            #pragma unroll
            for (int i = 0; i < 4; i++)
                #pragma unroll
                for (int j = 0; j < 2; j++) {
                    int cell = (hq + 4 * i) * 16 + sq + 8 * j;
                    parts[cell * 9 + g] = lo_f(acc[i][j]) + hi_f(acc[i][j]);
                }
        }
        __syncthreads();

        // ---- reduce + online softmax (thread t owns cell t)
        {
            int n = (tl < 8) ? n0 : n1;
            float sum = 0.f;
            #pragma unroll
            for (int gg = 0; gg < 8; gg++) sum += parts[t * 9 + gg];
            float sc = sum * QSCALE + block_bias[n * BSS + (tl & 7) * 16 + ss];

            float tm = sc;
            #pragma unroll
            for (int o = 8; o >= 1; o >>= 1)
                tm = fmaxf(tm, __shfl_xor_sync(0xffffffffu, tm, o, 16));
            float Mo = Mx[sh];
            float Mn = fmaxf(Mo, tm);
            float r  = __expf(Mo - Mn);
            float p  = __expf(sc - Mn);
            pp[sh * 17 + ss] = p;
            float psum = p;
            #pragma unroll
            for (int o = 8; o >= 1; o >>= 1)
                psum += __shfl_xor_sync(0xffffffffu, psum, o, 16);
            if (ss == 0) {
                Lx[sh] = Lx[sh] * r + psum;
                Mx[sh] = Mn;
                rr[sh] = r;
            }
        }
        __syncthreads();

        // ---- PV: rescale o, accumulate this tile's 16 s-rows
        #pragma unroll
        for (int i = 0; i < 4; i++) {
            ull rd = dup2(rr[hb + 4 * i]);
            #pragma unroll
            for (int k = 0; k < 4; k++) {
                ull tmp = 0ull;
                fma2(tmp, o2[i][k], rd);
                o2[i][k] = tmp;
            }
        }
        #pragma unroll
        for (int s = 0; s < 16; s++) {
            ull pd[4];
            #pragma unroll
            for (int i = 0; i < 4; i++)
                pd[i] = dup2(pp[(hb + 4 * i) * 17 + s]);
            ulonglong2 va = *(const ulonglong2*)&kt[s * TSTR + vb];
            ulonglong2 vc = *(const ulonglong2*)&kt[s * TSTR + vb + 64];
            #pragma unroll
            for (int i = 0; i < 4; i++) {
                fma2(o2[i][0], pd[i], va.x);
                fma2(o2[i][1], pd[i], va.y);
                fma2(o2[i][2], pd[i], vc.x);
                fma2(o2[i][3], pd[i], vc.y);
            }
        }

        // ---- block boundary / final epilogue
        if (tl == 7 || tl == 15) {
            int n = (tl == 7) ? n0 : n1;
            #pragma unroll
            for (int i = 0; i < 4; i++) {
                int h = hb + 4 * i;
                ulonglong2* dst = (ulonglong2*)(g_oacc + ((long)(n * HH + h)) * DVV);
                ulonglong2 v0; v0.x = o2[i][0]; v0.y = o2[i][1];
                ulonglong2 v1; v1.x = o2[i][2]; v1.y = o2[i][3];
                dst[vb]      = v0;
                dst[vb + 64] = v1;
                o2[i][0] = o2[i][1] = o2[i][2] = o2[i][3] = 0ull;
            }
            if (t < 16) {
                g_bm[n * HH + t] = Mx[t];
                g_bs[n * HH + t] = Lx[t];
                Mx[t] = -3e38f;
                Lx[t] = 0.f;
            }
            // next read of Mx/pp is ordered behind the loop-top barrier
        }

        if (tl + 2 < 16) issueT(tl + 2);
    }
}

// ---------------- combine: group b owns blocks b*16..b*16+15 ----------------
__global__ __launch_bounds__(512) void mla_combine_kernel(float* __restrict__ out)
{
    const int b = blockIdx.x, h = blockIdx.y, t = threadIdx.x;
    __shared__ float w[16];

    if (t < 16) {
        float m = g_bm[(b * 16 + t) * HH + h];
        float gmax = m;
        #pragma unroll
        for (int o = 8; o >= 1; o >>= 1)
            gmax = fmaxf(gmax, __shfl_xor_sync(0xffffu, gmax, o, 16));
        float e = __expf(m - gmax);
        float gsum = g_bs[(b * 16 + t) * HH + h] * e;
        #pragma unroll
        for (int o = 8; o >= 1; o >>= 1)
            gsum += __shfl_xor_sync(0xffffu, gsum, o, 16);
        w[t] = e / gsum;
    }
    __syncthreads();

    float v[16];
    #pragma unroll
    for (int j = 0; j < 16; j++)
        v[j] = g_oacc[((long)((b * 16 + j) * HH + h)) * DVV + t];

    float acc = 0.f;
    #pragma unroll
    for (int j = 0; j < 16; j++)
        acc += w[j] * v[j];
    out[((long)(b * HH + h)) * DVV + t] = acc;
}

// -----------------------------------------------------------------------------
extern "C" void kernel_launch(void* const* d_in, const int* in_sizes, int n_in,
                              void* d_out, int out_size)
{
    const float* query        = (const float*)d_in[0];
    const float* key_cache    = (const float*)d_in[1];
    const float* block_bias   = (const float*)d_in[3];
    const int*   block_list   = (const int*)d_in[4];
    const int*   block_groups = (const int*)d_in[5];
    float* out = (float*)d_out;

    cudaFuncSetAttribute(mla_fused_kernel,
                         cudaFuncAttributeMaxDynamicSharedMemorySize, SMEM_BYTES);

    mla_fused_kernel<<<NBLK / 2, 256, SMEM_BYTES>>>(
        query, key_cache, block_bias, block_list, block_groups);
    mla_combine_kernel<<<dim3(BQ, HH), 512>>>(out);
}

// round 16
// speedup vs baseline: 2.0093x; 2.0093x over previous
#include <cuda_runtime.h>
#include <math.h>
#include <cstdint>

// Problem constants
#define NBLK 512
#define NH   1024     // half-blocks (64 s-rows each)
#define BQ   32
#define HH   16
#define DD   576
#define DD4  144
#define DVV  512
#define BSS  128
#define QSCALE 0.07216878364870322f  // 192^-0.5

typedef unsigned long long ull;

// Scratch (device globals — no allocation allowed)
__device__ float g_oacc[NH * HH * DVV];   // 33.5 MB partial outputs (per half)
__device__ float g_bm[NH * HH];
__device__ float g_bs[NH * HH];

// ---------------- helpers ----------------
__device__ __forceinline__ uint32_t smem_u32(const void* p) {
    uint32_t a;
    asm("{ .reg .u64 t; cvta.to.shared.u64 t, %1; cvt.u32.u64 %0, t; }" : "=r"(a) : "l"(p));
    return a;
}
__device__ __forceinline__ void cp16(uint32_t dst, const void* src) {
    asm volatile("cp.async.cg.shared.global [%0], [%1], 16;" :: "r"(dst), "l"(src));
}
#define CP_COMMIT() asm volatile("cp.async.commit_group;" ::: "memory")
#define CP_WAIT(n)  asm volatile("cp.async.wait_group %0;" :: "n"(n) : "memory")

// compile-time dispatched wait (the "n" constraint needs a literal immediate)
__device__ __forceinline__ void cp_wait_dyn(int n) {
    switch (n) {
        case 0: CP_WAIT(0); break;
        case 1: CP_WAIT(1); break;
        case 2: CP_WAIT(2); break;
        case 3: CP_WAIT(3); break;
        case 4: CP_WAIT(4); break;
        case 5: CP_WAIT(5); break;
        case 6: CP_WAIT(6); break;
        case 7: CP_WAIT(7); break;
        default: CP_WAIT(8); break;
    }
}

__device__ __forceinline__ void fma2(ull& d, ull a, ull b) {
    asm("fma.rn.f32x2 %0, %1, %2, %0;" : "+l"(d) : "l"(a), "l"(b));
}
__device__ __forceinline__ float lo_f(ull v) { return __uint_as_float((unsigned)v); }
__device__ __forceinline__ float hi_f(ull v) { return __uint_as_float((unsigned)(v >> 32)); }
__device__ __forceinline__ ull dup2(float v) {
    unsigned u = __float_as_uint(v);
    return ((ull)u << 32) | u;
}

// ---------------- SMEM layout (bytes) ----------------
// kv   : 64 rows x 145 f4 = 148480                     [0, 148480)
// q    : 16 rows x 145 f4 = 37120                      [148480, 185600)
// parts: 1024 cells x 8 f = 32768                      [185600, 218368)
// attn : 16 h x 68 f = 4352                            [218368, 222720)
#define TSTR  145
#define QOFF  148480
#define PARTOFF 185600
#define ATTOFF 218368
#define ATT_STRIDE 68
#define SMEM_BYTES 222720

__global__ __launch_bounds__(512, 1) void mla_half_kernel(
    const float* __restrict__ query,
    const float* __restrict__ key_cache,
    const float* __restrict__ block_bias,
    const int* __restrict__ block_list,
    const int* __restrict__ block_groups)
{
    extern __shared__ char smem[];
    const uint32_t sbase = smem_u32(smem);
    const int t = threadIdx.x;
    const int n2 = blockIdx.x;
    const int n = n2 >> 1;            // source block
    const int half = n2 & 1;          // s-rows [half*64, half*64+64)
    const int b = block_groups[n];

    const float4* kvb4 = (const float4*)(key_cache + (long)block_list[n] * (BSS * DD))
                         + (long)(half * 64) * DD4;
    const float4* q4 = (const float4*)query + (long)(b * HH) * DD4;

    const float4* kvs4 = (const float4*)smem;
    const float4* qs4  = (const float4*)(smem + QOFF);
    float* parts = (float*)(smem + PARTOFF);
    float* attn  = (float*)(smem + ATTOFF);

    // ---- issue Q (group 0): 2304 f4 into stride-145 rows
    {
        #pragma unroll
        for (int j = 0; j < 5; j++) {
            int idx = t + j * 512;
            if (idx < 2304) {
                int row = idx / 144, col = idx - row * 144;
                cp16(sbase + QOFF + (unsigned)(row * TSTR + col) * 16,
                     q4 + (long)row * DD4 + col);
            }
        }
        CP_COMMIT();
    }
    // ---- issue all 9 KV chunks (groups 1..9): 64 rows x 16 f4 each
    #pragma unroll
    for (int c = 0; c < 9; c++) {
        #pragma unroll
        for (int j = 0; j < 2; j++) {
            int idx = t + j * 512;
            int row = idx >> 4, col = idx & 15;
            cp16(sbase + (unsigned)(row * TSTR + c * 16 + col) * 16,
                 kvb4 + (long)row * DD4 + c * 16 + col);
        }
        CP_COMMIT();
    }

    // ================= Pass A: scores, d-split by 8 groups =================
    // g = t>>6 owns d-window [c*64 + g*8, +8) per chunk (2 f4)
    // 64-thread group: tile h = hq+4i (i<4), s = sq+16j (j<4)
    const int g  = t >> 6;
    const int u  = t & 63;
    const int hq = u & 3;
    const int sq = u >> 2;    // 0..15

    ull acc2[4][4];
    #pragma unroll
    for (int i = 0; i < 4; i++)
        #pragma unroll
        for (int j = 0; j < 4; j++) acc2[i][j] = 0ull;

    #pragma unroll
    for (int c = 0; c < 9; c++) {
        cp_wait_dyn(8 - c);     // Q + chunks 0..c complete
        __syncthreads();
        #pragma unroll
        for (int k4 = 0; k4 < 2; k4++) {
            int col = c * 16 + g * 2 + k4;
            ull qp[4][2], kp[4][2];
            #pragma unroll
            for (int i = 0; i < 4; i++) {
                ulonglong2 qq = *(const ulonglong2*)&qs4[(hq + 4 * i) * TSTR + col];
                qp[i][0] = qq.x; qp[i][1] = qq.y;
            }
            #pragma unroll
            for (int j = 0; j < 4; j++) {
                ulonglong2 kk = *(const ulonglong2*)&kvs4[(sq + 16 * j) * TSTR + col];
                kp[j][0] = kk.x; kp[j][1] = kk.y;
            }
            #pragma unroll
            for (int i = 0; i < 4; i++)
                #pragma unroll
                for (int j = 0; j < 4; j++) {
                    fma2(acc2[i][j], qp[i][0], kp[j][0]);
                    fma2(acc2[i][j], qp[i][1], kp[j][1]);
                }
        }
    }

    // write d-partials (one time)
    #pragma unroll
    for (int i = 0; i < 4; i++)
        #pragma unroll
        for (int j = 0; j < 4; j++) {
            int cell = (hq + 4 * i) * 64 + sq + 16 * j;
            parts[cell * 8 + g] = lo_f(acc2[i][j]) + hi_f(acc2[i][j]);
        }
    __syncthreads();

    // reduce partials -> attn (2 cells per thread)
    #pragma unroll
    for (int r = 0; r < 2; r++) {
        int cell = t + 512 * r;
        int h = cell >> 6, s = cell & 63;
        float sum = 0.f;
        #pragma unroll
        for (int gg = 0; gg < 8; gg++) sum += parts[cell * 8 + gg];
        attn[h * ATT_STRIDE + s] =
            sum * QSCALE + block_bias[n * BSS + half * 64 + s];
    }
    __syncthreads();

    // ================= Pass B: softmax over this half's 64 s ===============
    {
        int h = t >> 5, ln = t & 31;   // one warp per head
        float a0 = attn[h * ATT_STRIDE + ln];
        float a1 = attn[h * ATT_STRIDE + ln + 32];
        float m = fmaxf(a0, a1);
        #pragma unroll
        for (int o = 16; o >= 1; o >>= 1)
            m = fmaxf(m, __shfl_xor_sync(0xffffffffu, m, o));
        float p0 = __expf(a0 - m);
        float p1 = __expf(a1 - m);
        attn[h * ATT_STRIDE + ln]      = p0;
        attn[h * ATT_STRIDE + ln + 32] = p1;
        float l = p0 + p1;
        #pragma unroll
        for (int o = 16; o >= 1; o >>= 1)
            l += __shfl_xor_sync(0xffffffffu, l, o);
        if (ln == 0) {
            g_bm[n2 * HH + h] = m;
            g_bs[n2 * HH + h] = l;
        }
    }
    __syncthreads();

    // ================= Pass C: o = p @ v from RESIDENT smem ================
    // thread tile: h = hb + 4*i, v f4 column vb (0..127)
    const int hb = t & 3;
    const int vb = t >> 2;

    ull o2[4][2];
    #pragma unroll
    for (int i = 0; i < 4; i++) { o2[i][0] = 0ull; o2[i][1] = 0ull; }

    #pragma unroll 4
    for (int s = 0; s < 64; s++) {
        ull pd[4];
        #pragma unroll
        for (int i = 0; i < 4; i++)
            pd[i] = dup2(attn[(hb + 4 * i) * ATT_STRIDE + s]);
        ulonglong2 vv = *(const ulonglong2*)&kvs4[s * TSTR + vb];
        #pragma unroll
        for (int i = 0; i < 4; i++) {
            fma2(o2[i][0], pd[i], vv.x);
            fma2(o2[i][1], pd[i], vv.y);
        }
    }

    // store partials
    #pragma unroll
    for (int i = 0; i < 4; i++) {
        int h = hb + 4 * i;
        ulonglong2* dst = (ulonglong2*)(g_oacc + ((long)(n2 * HH + h)) * DVV);
        ulonglong2 v; v.x = o2[i][0]; v.y = o2[i][1];
        dst[vb] = v;
    }
}

// ---------------- combine: group b owns halves n2 = b*32 .. b*32+31 --------
__global__ __launch_bounds__(256) void mla_combine_kernel(float* __restrict__ out)
{
    const int b = blockIdx.x, h = blockIdx.y, t = threadIdx.x;
    __shared__ float w[32];

    if (t < 32) {
        float m = g_bm[(b * 32 + t) * HH + h];
        float gmax = m;
        #pragma unroll
        for (int o = 16; o >= 1; o >>= 1)
            gmax = fmaxf(gmax, __shfl_xor_sync(0xffffffffu, gmax, o));
        float e = __expf(m - gmax);
        float gsum = g_bs[(b * 32 + t) * HH + h] * e;
        #pragma unroll
        for (int o = 16; o >= 1; o >>= 1)
            gsum += __shfl_xor_sync(0xffffffffu, gsum, o);
        w[t] = e / gsum;
    }
    __syncthreads();

    float2 acc = make_float2(0.f, 0.f);
    #pragma unroll
    for (int j = 0; j < 32; j++) {
        float ww = w[j];
        float2 v = ((const float2*)(g_oacc + ((long)((b * 32 + j) * HH + h)) * DVV))[t];
        acc.x += ww * v.x;
        acc.y += ww * v.y;
    }
    ((float2*)(out + ((long)(b * HH + h)) * DVV))[t] = acc;
}

// -----------------------------------------------------------------------------
extern "C" void kernel_launch(void* const* d_in, const int* in_sizes, int n_in,
                              void* d_out, int out_size)
{
    const float* query        = (const float*)d_in[0];
    const float* key_cache    = (const float*)d_in[1];
    const float* block_bias   = (const float*)d_in[3];
    const int*   block_list   = (const int*)d_in[4];
    const int*   block_groups = (const int*)d_in[5];
    float* out = (float*)d_out;

    cudaFuncSetAttribute(mla_half_kernel,
                         cudaFuncAttributeMaxDynamicSharedMemorySize, SMEM_BYTES);

    mla_half_kernel<<<NH, 512, SMEM_BYTES>>>(
        query, key_cache, block_bias, block_list, block_groups);
    mla_combine_kernel<<<dim3(BQ, HH), 256>>>(out);
}

// round 17
// speedup vs baseline: 2.5703x; 1.2792x over previous
#include <cuda_runtime.h>
#include <math.h>
#include <cstdint>

// Problem constants
#define NBLK 512
#define BQ   32
#define HH   16
#define DD   576
#define DD4  144
#define DVV  512
#define BSS  128
#define QSCALE 0.07216878364870322f  // 192^-0.5

typedef unsigned long long ull;

// Scratch (device globals — no allocation allowed)
__device__ float g_oacc[NBLK * HH * DVV];
__device__ float g_bm[NBLK * HH];
__device__ float g_bs[NBLK * HH];

// ---------------- helpers ----------------
__device__ __forceinline__ uint32_t smem_u32(const void* p) {
    uint32_t a;
    asm("{ .reg .u64 t; cvta.to.shared.u64 t, %1; cvt.u32.u64 %0, t; }" : "=r"(a) : "l"(p));
    return a;
}
__device__ __forceinline__ void cp16(uint32_t dst, const void* src) {
    asm volatile("cp.async.cg.shared.global [%0], [%1], 16;" :: "r"(dst), "l"(src));
}
#define CP_COMMIT() asm volatile("cp.async.commit_group;" ::: "memory")
#define CP_WAIT(n)  asm volatile("cp.async.wait_group %0;" :: "n"(n) : "memory")

__device__ __forceinline__ void fma2(ull& d, ull a, ull b) {
    asm("fma.rn.f32x2 %0, %1, %2, %0;" : "+l"(d) : "l"(a), "l"(b));
}
__device__ __forceinline__ float lo_f(ull v) { return __uint_as_float((unsigned)v); }
__device__ __forceinline__ float hi_f(ull v) { return __uint_as_float((unsigned)(v >> 32)); }
__device__ __forceinline__ ull dup2(float v) {
    unsigned u = __float_as_uint(v);
    return ((ull)u << 32) | u;
}

// ---------------- SMEM layout (bytes) ----------------
// [0, 36864)      : K chunk double buffer: buf b at b*18432, 128 rows x 9 float4
//                   (Pass C: V double buffer, buf b at b*16384, 8 rows x 128 f4)
// [36864, 41472)  : Q chunk double buffer: buf b at QOFF + b*2304, 16 x 9 float4
// [41472, 49920)  : attn f32 [16][132]
#define KBUFB 18432
#define KSTR  9
#define QOFF  36864
#define QBUFB 2304
#define ATTOFF 41472
#define ATT_STRIDE 132
#define SMEM_BYTES 49920

#define CHUNK_F4 8    // 32 d-floats per chunk
#define NCH 18        // 576 / 32

__global__ __launch_bounds__(128, 4) void mla_block_kernel(
    const float* __restrict__ query,
    const float* __restrict__ key_cache,
    const float* __restrict__ block_bias,
    const int* __restrict__ block_list,
    const int* __restrict__ block_groups)
{
    extern __shared__ char smem[];
    const uint32_t sbase = smem_u32(smem);
    const int t = threadIdx.x;
    const int n = blockIdx.x;
    const int b = block_groups[n];
    const float4* kvb4 = (const float4*)(key_cache + (long)block_list[n] * (BSS * DD));
    const float4* q4 = (const float4*)query;
    float* attn = (float*)(smem + ATTOFF);

    // q loader mapping
    const int ls = t >> 3, lk = t & 7;

    // ---- Pass A issue: chunk c -> buffer c&1 (K 1024 f4 + Q 16 f4)
    auto issueA = [&](int c) {
        uint32_t kb = sbase + (unsigned)(c & 1) * KBUFB;
        #pragma unroll
        for (int j = 0; j < 8; j++) {
            int i = t + j * 128;
            int s = i >> 3, k = i & 7;
            cp16(kb + (unsigned)(s * KSTR + k) * 16,
                 kvb4 + (long)s * DD4 + c * CHUNK_F4 + k);
        }
        cp16(sbase + QOFF + (unsigned)(c & 1) * QBUFB + (unsigned)(ls * KSTR + lk) * 16,
             q4 + (long)(b * HH + ls) * DD4 + c * CHUNK_F4 + lk);
        CP_COMMIT();
    };
    // ---- Pass C issue: V tile tl -> buffer tl&1 (8 rows x 128 f4)
    auto issueC = [&](int tl) {
        uint32_t vbuf = sbase + (unsigned)(tl & 1) * 16384;
        #pragma unroll
        for (int j = 0; j < 8; j++) {
            int i = t + j * 128;
            int r = i >> 7, col = i & 127;
            cp16(vbuf + (unsigned)i * 16,
                 kvb4 + (long)(tl * 8 + r) * DD4 + col);
        }
        CP_COMMIT();
    };

    // ================= Pass A: attn = scale * q . kv =======================
    // thread tile: h = hq + 4*i, s = sq + 32*j  (conflict-free LDS)
    const int hq = t & 3;
    const int sq = t >> 2;   // 0..31

    ull acc2[4][4];
    #pragma unroll
    for (int i = 0; i < 4; i++)
        #pragma unroll
        for (int j = 0; j < 4; j++) acc2[i][j] = 0ull;

    issueA(0);
    issueA(1);

    for (int c = 0; c < NCH; c++) {
        if (c < NCH - 1) CP_WAIT(1); else CP_WAIT(0);
        __syncthreads();

        // Early V prefetch during last K chunk's compute (buffer 0 free).
        if (c == NCH - 1) issueC(0);

        const float4* kvs4 = (const float4*)(smem + (c & 1) * KBUFB);
        const float4* qc4  = (const float4*)(smem + QOFF + (c & 1) * QBUFB);

        #pragma unroll
        for (int k4 = 0; k4 < 8; k4++) {
            ull qp[4][2], kp[4][2];
            #pragma unroll
            for (int i = 0; i < 4; i++) {
                ulonglong2 qq = *(const ulonglong2*)&qc4[(hq + 4 * i) * KSTR + k4];
                qp[i][0] = qq.x; qp[i][1] = qq.y;
            }
            #pragma unroll
            for (int j = 0; j < 4; j++) {
                ulonglong2 kk = *(const ulonglong2*)&kvs4[(sq + 32 * j) * KSTR + k4];
                kp[j][0] = kk.x; kp[j][1] = kk.y;
            }
            #pragma unroll
            for (int i = 0; i < 4; i++)
                #pragma unroll
                for (int j = 0; j < 4; j++) {
                    fma2(acc2[i][j], qp[i][0], kp[j][0]);
                    fma2(acc2[i][j], qp[i][1], kp[j][1]);
                }
        }
        __syncthreads();
        if (c + 2 < NCH) issueA(c + 2);
    }

    // merge lo+hi, apply scale, add bias, write attn
    #pragma unroll
    for (int j = 0; j < 4; j++) {
        int s = sq + 32 * j;
        float bias = block_bias[n * BSS + s];
        #pragma unroll
        for (int i = 0; i < 4; i++) {
            int h = hq + 4 * i;
            attn[h * ATT_STRIDE + s] =
                (lo_f(acc2[i][j]) + hi_f(acc2[i][j])) * QSCALE + bias;
        }
    }
    __syncthreads();

    // V tile 1 (buffer 1 region free: K buf1 fully consumed pre-barrier)
    issueC(1);

    // ================= Pass B: per-(n,h) softmax ===========================
    {
        int h = t >> 3, ln = t & 7;
        float m = -1e30f;
        #pragma unroll
        for (int r = 0; r < 16; r++)
            m = fmaxf(m, attn[h * ATT_STRIDE + ln + r * 8]);
        #pragma unroll
        for (int o = 4; o >= 1; o >>= 1)
            m = fmaxf(m, __shfl_xor_sync(0xffffffffu, m, o, 8));
        float l = 0.f;
        #pragma unroll
        for (int r = 0; r < 16; r++) {
            int idx = h * ATT_STRIDE + ln + r * 8;
            float p = __expf(attn[idx] - m);
            attn[idx] = p;
            l += p;
        }
        #pragma unroll
        for (int o = 4; o >= 1; o >>= 1)
            l += __shfl_xor_sync(0xffffffffu, l, o, 8);
        if (ln == 0) {
            g_bm[n * HH + h] = m;
            g_bs[n * HH + h] = l;
        }
    }

    // ================= Pass C: o = p @ v (f32x2, 16 tiles of 8 rows) =======
    const int hb = t & 3;
    const int vb = t >> 2;   // 0..31

    ull o2[4][8];
    #pragma unroll
    for (int i = 0; i < 4; i++)
        #pragma unroll
        for (int p = 0; p < 8; p++) o2[i][p] = 0ull;

    for (int tl = 0; tl < 16; tl++) {
        if (tl < 15) CP_WAIT(1); else CP_WAIT(0);
        __syncthreads();

        const float4* vs4 = (const float4*)(smem + (tl & 1) * 16384);
        #pragma unroll
        for (int s = 0; s < 8; s++) {
            ull pd[4];
            #pragma unroll
            for (int i = 0; i < 4; i++)
                pd[i] = dup2(attn[(hb + 4 * i) * ATT_STRIDE + tl * 8 + s]);
            #pragma unroll
            for (int cc = 0; cc < 4; cc++) {
                ulonglong2 vv = *(const ulonglong2*)&vs4[s * 128 + vb + cc * 32];
                #pragma unroll
                for (int i = 0; i < 4; i++) {
                    fma2(o2[i][2 * cc],     pd[i], vv.x);
                    fma2(o2[i][2 * cc + 1], pd[i], vv.y);
                }
            }
        }
        __syncthreads();
        if (tl + 2 < 16) issueC(tl + 2);
    }

    // store partials (each thread: 4 float4s per h at column vb + cc*32)
    #pragma unroll
    for (int i = 0; i < 4; i++) {
        int h = hb + 4 * i;
        ulonglong2* dst = (ulonglong2*)(g_oacc + ((long)(n * HH + h)) * DVV);
        #pragma unroll
        for (int cc = 0; cc < 4; cc++) {
            ulonglong2 v; v.x = o2[i][2 * cc]; v.y = o2[i][2 * cc + 1];
            dst[vb + cc * 32] = v;
        }
    }
}

// ---------------- combine: group b owns blocks b*16..b*16+15 ----------------
// 512 threads, thread owns one v-float; all 16 block loads in flight.
__global__ __launch_bounds__(512) void mla_combine_kernel(float* __restrict__ out)
{
    const int b = blockIdx.x, h = blockIdx.y, t = threadIdx.x;
    __shared__ float w[16];

    if (t < 16) {
        float m = g_bm[(b * 16 + t) * HH + h];
        float gmax = m;
        #pragma unroll
        for (int o = 8; o >= 1; o >>= 1)
            gmax = fmaxf(gmax, __shfl_xor_sync(0xffffu, gmax, o, 16));
        float e = __expf(m - gmax);
        float gsum = g_bs[(b * 16 + t) * HH + h] * e;
        #pragma unroll
        for (int o = 8; o >= 1; o >>= 1)
            gsum += __shfl_xor_sync(0xffffu, gsum, o, 16);
        w[t] = e / gsum;
    }
    __syncthreads();

    float v[16];
    #pragma unroll
    for (int j = 0; j < 16; j++)
        v[j] = g_oacc[((long)((b * 16 + j) * HH + h)) * DVV + t];

    float acc = 0.f;
    #pragma unroll
    for (int j = 0; j < 16; j++)
        acc += w[j] * v[j];
    out[((long)(b * HH + h)) * DVV + t] = acc;
}

// -----------------------------------------------------------------------------
extern "C" void kernel_launch(void* const* d_in, const int* in_sizes, int n_in,
                              void* d_out, int out_size)
{
    const float* query        = (const float*)d_in[0];
    const float* key_cache    = (const float*)d_in[1];
    const float* block_bias   = (const float*)d_in[3];
    const int*   block_list   = (const int*)d_in[4];
    const int*   block_groups = (const int*)d_in[5];
    float* out = (float*)d_out;

    cudaFuncSetAttribute(mla_block_kernel,
                         cudaFuncAttributeMaxDynamicSharedMemorySize, SMEM_BYTES);

    mla_block_kernel<<<NBLK, 128, SMEM_BYTES>>>(
        query, key_cache, block_bias, block_list, block_groups);
    mla_combine_kernel<<<dim3(BQ, HH), 512>>>(out);
}